// round 1
// baseline (speedup 1.0000x reference)
#include <cuda_runtime.h>
#include <math.h>

// Problem constants
#define BB   8
#define CC   64
#define C3   192
#define ZZ   32
#define SS   32768          // 32*32*32
#define HEADS 8
#define CH   8              // CC / HEADS
#define EPSN 1e-12f

// -------- device scratch (allocation-free rule: __device__ globals) --------
__device__ float g_pw [BB * C3 * SS];   // pointwise conv output  (201 MB)
__device__ float g_qkv[BB * C3 * SS];   // depthwise conv output  (201 MB)
__device__ float g_part[BB * HEADS * 8 * 80]; // per-chunk partial reductions
__device__ float g_M  [BB * CC * CC];   // folded (w_proj x attn) matrices

// ===========================================================================
// K1: pointwise conv  g_pw[b][o][s] = sum_ci w_qkv[o][ci] * x[b][ci][s]
//     grid (128, 8), block 256 ; w in 48KB static smem, x in 64 registers
// ===========================================================================
__global__ __launch_bounds__(256) void k1_pw(const float* __restrict__ x,
                                             const float* __restrict__ w_qkv)
{
    __shared__ float w_sh[C3 * CC];            // 12288 floats = 48KB
    const int tid = threadIdx.x;
    for (int i = tid; i < C3 * CC; i += 256) w_sh[i] = w_qkv[i];
    __syncthreads();

    const int b = blockIdx.y;
    const int s = blockIdx.x * 256 + tid;

    float xr[CC];
#pragma unroll
    for (int ci = 0; ci < CC; ci++)
        xr[ci] = x[((size_t)(b * CC + ci)) * SS + s];

    float* out = g_pw + ((size_t)b * C3) * SS + s;
    for (int o = 0; o < C3; o++) {
        const float4* w4 = (const float4*)(w_sh + o * CC);
        float acc = 0.f;
#pragma unroll
        for (int j = 0; j < CC / 4; j++) {
            float4 w = w4[j];
            acc += w.x * xr[4 * j + 0];
            acc += w.y * xr[4 * j + 1];
            acc += w.z * xr[4 * j + 2];
            acc += w.w * xr[4 * j + 3];
        }
        out[(size_t)o * SS] = acc;
    }
}

// ===========================================================================
// K2: depthwise 3x3x3, pad SAME.  One block = (b, ch, z-slab of 8).
//     shared tile: 10 x 34 x 34 with halo (46.2 KB)
// ===========================================================================
__global__ __launch_bounds__(256) void k2_dw(const float* __restrict__ w_dw)
{
    __shared__ float sh[10 * 34 * 34];         // 11560 floats
    const int tid = threadIdx.x;
    const int z0  = blockIdx.x * 8;
    const int ch  = blockIdx.y;
    const int b   = blockIdx.z;

    const float* in = g_pw + ((size_t)(b * C3 + ch)) * SS;

    for (int i = tid; i < 10 * 34 * 34; i += 256) {
        int p  = i / 1156;
        int r  = i - p * 1156;
        int yy = r / 34;
        int xx = r - yy * 34;
        int gz = z0 - 1 + p, gy = yy - 1, gx = xx - 1;
        float v = 0.f;
        if (gz >= 0 && gz < ZZ && gy >= 0 && gy < ZZ && gx >= 0 && gx < ZZ)
            v = in[gz * 1024 + gy * 32 + gx];
        sh[i] = v;
    }

    float wr[27];
#pragma unroll
    for (int j = 0; j < 27; j++) wr[j] = w_dw[ch * 27 + j];
    __syncthreads();

    float* out = g_qkv + ((size_t)(b * C3 + ch)) * SS;
    for (int i = tid; i < 8 * 1024; i += 256) {
        int zi = i >> 10;
        int r  = i & 1023;
        int y  = r >> 5;
        int xp = r & 31;
        float acc = 0.f;
#pragma unroll
        for (int dz = 0; dz < 3; dz++)
#pragma unroll
            for (int dy = 0; dy < 3; dy++)
#pragma unroll
                for (int dx = 0; dx < 3; dx++)
                    acc += wr[dz * 9 + dy * 3 + dx] *
                           sh[(zi + dz) * 1156 + (y + dy) * 34 + (xp + dx)];
        out[(z0 + zi) * 1024 + y * 32 + xp] = acc;
    }
}

// ===========================================================================
// K3: per (b,h) gram reductions over s.
//     partial layout per (bh, chunk): [0..63]=dot[c][d], [64..71]=sumsq q_c,
//     [72..79]=sumsq k_d.  grid (8 chunks, 64 bh), block 256.
// ===========================================================================
__global__ __launch_bounds__(256) void k3_red()
{
    const int tid   = threadIdx.x;
    const int chunk = blockIdx.x;
    const int bh    = blockIdx.y;
    const int b = bh >> 3, h = bh & 7;

    const float* qp = g_qkv + ((size_t)(b * C3 + h * CH)) * SS;
    const float* kp = g_qkv + ((size_t)(b * C3 + CC + h * CH)) * SS;

    float acc[80];
#pragma unroll
    for (int i = 0; i < 80; i++) acc[i] = 0.f;

    int s = chunk * 4096 + tid;
#pragma unroll 1
    for (int it = 0; it < 16; it++, s += 256) {
        float qv[CH], kv[CH];
#pragma unroll
        for (int c = 0; c < CH; c++) qv[c] = qp[(size_t)c * SS + s];
#pragma unroll
        for (int d = 0; d < CH; d++) kv[d] = kp[(size_t)d * SS + s];
#pragma unroll
        for (int c = 0; c < CH; c++)
#pragma unroll
            for (int d = 0; d < CH; d++)
                acc[c * 8 + d] += qv[c] * kv[d];
#pragma unroll
        for (int c = 0; c < CH; c++) acc[64 + c] += qv[c] * qv[c];
#pragma unroll
        for (int d = 0; d < CH; d++) acc[72 + d] += kv[d] * kv[d];
    }

    __shared__ float red[8][80];
    const int lane = tid & 31, warp = tid >> 5;
#pragma unroll
    for (int i = 0; i < 80; i++) {
        float v = acc[i];
        v += __shfl_down_sync(0xffffffffu, v, 16);
        v += __shfl_down_sync(0xffffffffu, v, 8);
        v += __shfl_down_sync(0xffffffffu, v, 4);
        v += __shfl_down_sync(0xffffffffu, v, 2);
        v += __shfl_down_sync(0xffffffffu, v, 1);
        if (lane == 0) red[warp][i] = v;
    }
    __syncthreads();
    if (tid < 80) {
        float v = 0.f;
#pragma unroll
        for (int w = 0; w < 8; w++) v += red[w][tid];
        g_part[(bh * 8 + chunk) * 80 + tid] = v;
    }
}

// ===========================================================================
// K4: finish reductions, softmax, fold with w_proj -> g_M[b][64][64]
//     grid 8 (b), block 64.  thread t = (h, c)
// ===========================================================================
__global__ __launch_bounds__(64) void k4_attn(const float* __restrict__ w_proj,
                                              const float* __restrict__ temperature)
{
    __shared__ float attn_sh[CC * CH];         // [h*8+c][d]
    const int b = blockIdx.x;
    const int t = threadIdx.x;
    const int h = t >> 3, c = t & 7;

    float dot[CH] = {0, 0, 0, 0, 0, 0, 0, 0};
    float nqs = 0.f;
    float nks[CH] = {0, 0, 0, 0, 0, 0, 0, 0};
#pragma unroll
    for (int chunk = 0; chunk < 8; chunk++) {
        const float* p = g_part + (((b * 8 + h) * 8) + chunk) * 80;
#pragma unroll
        for (int d = 0; d < CH; d++) dot[d] += p[c * 8 + d];
        nqs += p[64 + c];
#pragma unroll
        for (int d = 0; d < CH; d++) nks[d] += p[72 + d];
    }
    const float temp = temperature[b];
    const float nq = fmaxf(sqrtf(nqs), EPSN);
    float logit[CH];
    float m = -INFINITY;
#pragma unroll
    for (int d = 0; d < CH; d++) {
        float nk = fmaxf(sqrtf(nks[d]), EPSN);
        logit[d] = dot[d] / (nq * nk) * temp;
        m = fmaxf(m, logit[d]);
    }
    float sum = 0.f;
#pragma unroll
    for (int d = 0; d < CH; d++) { logit[d] = expf(logit[d] - m); sum += logit[d]; }
    const float inv = 1.f / sum;
#pragma unroll
    for (int d = 0; d < CH; d++) attn_sh[(h * 8 + c) * 8 + d] = logit[d] * inv;
    __syncthreads();

    // M[co][h2*8+d] = sum_c w_proj[co][h2*8+c] * attn[h2][c][d]
    for (int idx = t; idx < CC * CC; idx += 64) {
        int co = idx >> 6, j = idx & 63;
        int h2 = j >> 3, d = j & 7;
        float acc = 0.f;
#pragma unroll
        for (int cc = 0; cc < CH; cc++)
            acc += w_proj[co * CC + h2 * 8 + cc] * attn_sh[(h2 * 8 + cc) * 8 + d];
        g_M[b * CC * CC + idx] = acc;
    }
}

// ===========================================================================
// K5: out[b][co][s] = sum_j M[b][co][j] * v[b][j][s]
//     grid (128, 8), block 256.  v in 64 registers, M in 16KB smem
// ===========================================================================
__global__ __launch_bounds__(256) void k5_out(float* __restrict__ out)
{
    __shared__ float M_sh[CC * CC];            // 4096 floats = 16KB
    const int tid = threadIdx.x;
    const int b = blockIdx.y;
    const int s = blockIdx.x * 256 + tid;

    for (int i = tid; i < CC * CC; i += 256) M_sh[i] = g_M[b * CC * CC + i];
    __syncthreads();

    float vr[CC];
#pragma unroll
    for (int j = 0; j < CC; j++)
        vr[j] = g_qkv[((size_t)(b * C3 + 2 * CC + j)) * SS + s];

    float* op = out + ((size_t)b * CC) * SS + s;
    for (int co = 0; co < CC; co++) {
        const float4* m4 = (const float4*)(M_sh + co * CC);
        float acc = 0.f;
#pragma unroll
        for (int j = 0; j < CC / 4; j++) {
            float4 m = m4[j];
            acc += m.x * vr[4 * j + 0];
            acc += m.y * vr[4 * j + 1];
            acc += m.z * vr[4 * j + 2];
            acc += m.w * vr[4 * j + 3];
        }
        op[(size_t)co * SS] = acc;
    }
}

// ===========================================================================
extern "C" void kernel_launch(void* const* d_in, const int* in_sizes, int n_in,
                              void* d_out, int out_size)
{
    const float* x     = (const float*)d_in[0];
    const float* w_qkv = (const float*)d_in[1];
    const float* w_dw  = (const float*)d_in[2];
    const float* w_proj= (const float*)d_in[3];
    const float* temp  = (const float*)d_in[4];
    float* out = (float*)d_out;

    k1_pw  <<<dim3(SS / 256, BB), 256>>>(x, w_qkv);
    k2_dw  <<<dim3(ZZ / 8, C3, BB), 256>>>(w_dw);
    k3_red <<<dim3(8, BB * HEADS), 256>>>();
    k4_attn<<<BB, 64>>>(w_proj, temp);
    k5_out <<<dim3(SS / 256, BB), 256>>>(out);
}

// round 2
// speedup vs baseline: 1.0712x; 1.0712x over previous
#include <cuda_runtime.h>
#include <cuda_fp16.h>
#include <math.h>

// Problem constants
#define BB   8
#define CC   64
#define C3   192
#define ZZ   32
#define SS   32768          // 32*32*32
#define HEADS 8
#define CH   8              // CC / HEADS
#define NCHUNK 4
#define EPSN 1e-12f

// -------- device scratch (allocation-free rule: __device__ globals) --------
__device__ __half g_pw [BB * C3 * SS];             // pointwise output (100 MB)
__device__ __half g_qkv[BB * C3 * SS];             // depthwise output (100 MB)
__device__ float  g_part[BB * HEADS * NCHUNK * 80];// per-chunk partial reductions

// ===========================================================================
// K1: pointwise conv  g_pw[b][o][s] = sum_ci w_qkv[o][ci] * x[b][ci][s]
//     grid (128, 8), block 256 ; w in 48KB smem, x in 64 registers, half out
// ===========================================================================
__global__ __launch_bounds__(256) void k1_pw(const float* __restrict__ x,
                                             const float* __restrict__ w_qkv)
{
    __shared__ float w_sh[C3 * CC];            // 48KB
    const int tid = threadIdx.x;
    for (int i = tid; i < C3 * CC; i += 256) w_sh[i] = w_qkv[i];
    __syncthreads();

    const int b = blockIdx.y;
    const int s = blockIdx.x * 256 + tid;

    float xr[CC];
#pragma unroll
    for (int ci = 0; ci < CC; ci++)
        xr[ci] = x[((size_t)(b * CC + ci)) * SS + s];

    __half* out = g_pw + ((size_t)b * C3) * SS + s;
    for (int o = 0; o < C3; o++) {
        const float4* w4 = (const float4*)(w_sh + o * CC);
        float acc = 0.f;
#pragma unroll
        for (int j = 0; j < CC / 4; j++) {
            float4 w = w4[j];
            acc += w.x * xr[4 * j + 0];
            acc += w.y * xr[4 * j + 1];
            acc += w.z * xr[4 * j + 2];
            acc += w.w * xr[4 * j + 3];
        }
        out[(size_t)o * SS] = __float2half_rn(acc);
    }
}

// ===========================================================================
// K2: depthwise 3x3x3, pad SAME. One block = (b, ch, z-slab of 8).
//     shared tile: 10 x 34 x 34 fp32 (46.2 KB), global staging half
// ===========================================================================
__global__ __launch_bounds__(256) void k2_dw(const float* __restrict__ w_dw)
{
    __shared__ float sh[10 * 34 * 34];
    const int tid = threadIdx.x;
    const int z0  = blockIdx.x * 8;
    const int ch  = blockIdx.y;
    const int b   = blockIdx.z;

    const __half* in = g_pw + ((size_t)(b * C3 + ch)) * SS;

    for (int i = tid; i < 10 * 34 * 34; i += 256) {
        int p  = i / 1156;
        int r  = i - p * 1156;
        int yy = r / 34;
        int xx = r - yy * 34;
        int gz = z0 - 1 + p, gy = yy - 1, gx = xx - 1;
        float v = 0.f;
        if (gz >= 0 && gz < ZZ && gy >= 0 && gy < ZZ && gx >= 0 && gx < ZZ)
            v = __half2float(in[gz * 1024 + gy * 32 + gx]);
        sh[i] = v;
    }

    float wr[27];
#pragma unroll
    for (int j = 0; j < 27; j++) wr[j] = w_dw[ch * 27 + j];
    __syncthreads();

    __half* out = g_qkv + ((size_t)(b * C3 + ch)) * SS;
    for (int i = tid; i < 8 * 1024; i += 256) {
        int zi = i >> 10;
        int r  = i & 1023;
        int y  = r >> 5;
        int xp = r & 31;
        float acc = 0.f;
#pragma unroll
        for (int dz = 0; dz < 3; dz++)
#pragma unroll
            for (int dy = 0; dy < 3; dy++)
#pragma unroll
                for (int dx = 0; dx < 3; dx++)
                    acc += wr[dz * 9 + dy * 3 + dx] *
                           sh[(zi + dz) * 1156 + (y + dy) * 34 + (xp + dx)];
        out[(z0 + zi) * 1024 + y * 32 + xp] = __float2half_rn(acc);
    }
}

// ===========================================================================
// K3: per (b,h) gram reductions over s (4 chunks of 8192).
//     partial layout per (bh, chunk): [0..63]=dot[c][d], [64..71]=|q_c|^2,
//     [72..79]=|k_d|^2.  grid (4, 64), block 256.
// ===========================================================================
__global__ __launch_bounds__(256) void k3_red()
{
    const int tid   = threadIdx.x;
    const int chunk = blockIdx.x;
    const int bh    = blockIdx.y;
    const int b = bh >> 3, h = bh & 7;

    const __half* qp = g_qkv + ((size_t)(b * C3 + h * CH)) * SS;
    const __half* kp = g_qkv + ((size_t)(b * C3 + CC + h * CH)) * SS;

    float acc[80];
#pragma unroll
    for (int i = 0; i < 80; i++) acc[i] = 0.f;

    int s = chunk * 8192 + tid;
#pragma unroll 1
    for (int it = 0; it < 32; it++, s += 256) {
        float qv[CH], kv[CH];
#pragma unroll
        for (int c = 0; c < CH; c++) qv[c] = __half2float(qp[(size_t)c * SS + s]);
#pragma unroll
        for (int d = 0; d < CH; d++) kv[d] = __half2float(kp[(size_t)d * SS + s]);
#pragma unroll
        for (int c = 0; c < CH; c++)
#pragma unroll
            for (int d = 0; d < CH; d++)
                acc[c * 8 + d] += qv[c] * kv[d];
#pragma unroll
        for (int c = 0; c < CH; c++) acc[64 + c] += qv[c] * qv[c];
#pragma unroll
        for (int d = 0; d < CH; d++) acc[72 + d] += kv[d] * kv[d];
    }

    __shared__ float red[8][80];
    const int lane = tid & 31, warp = tid >> 5;
#pragma unroll
    for (int i = 0; i < 80; i++) {
        float v = acc[i];
        v += __shfl_down_sync(0xffffffffu, v, 16);
        v += __shfl_down_sync(0xffffffffu, v, 8);
        v += __shfl_down_sync(0xffffffffu, v, 4);
        v += __shfl_down_sync(0xffffffffu, v, 2);
        v += __shfl_down_sync(0xffffffffu, v, 1);
        if (lane == 0) red[warp][i] = v;
    }
    __syncthreads();
    if (tid < 80) {
        float v = 0.f;
#pragma unroll
        for (int w = 0; w < 8; w++) v += red[w][tid];
        g_part[(bh * NCHUNK + chunk) * 80 + tid] = v;
    }
}

// ===========================================================================
// K5: prologue (per block): finish reduction -> softmax -> M = w_proj x attn
//     main: out[b][co][s] = sum_j M[co][j] * v[b][j][s]
//     grid (128, 8), block 256.
// ===========================================================================
__global__ __launch_bounds__(256) void k5_out(const float* __restrict__ w_proj,
                                              const float* __restrict__ temperature,
                                              float* __restrict__ out)
{
    __shared__ float attn_sh[CC * CH];         // [(h*8+c)*8 + d]
    __shared__ float M_sh[CC * CC];            // 16KB
    const int tid = threadIdx.x;
    const int b = blockIdx.y;
    const int s = blockIdx.x * 256 + tid;

    // -- prologue 1: per (h,c) softmax row from partials --
    if (tid < CC) {
        const int h = tid >> 3, c = tid & 7;
        float dot[CH] = {0,0,0,0,0,0,0,0};
        float nqs = 0.f;
        float nks[CH] = {0,0,0,0,0,0,0,0};
#pragma unroll
        for (int chunk = 0; chunk < NCHUNK; chunk++) {
            const float* p = g_part + (((b * 8 + h) * NCHUNK) + chunk) * 80;
#pragma unroll
            for (int d = 0; d < CH; d++) dot[d] += p[c * 8 + d];
            nqs += p[64 + c];
#pragma unroll
            for (int d = 0; d < CH; d++) nks[d] += p[72 + d];
        }
        const float temp = temperature[b];
        const float nq = fmaxf(sqrtf(nqs), EPSN);
        float logit[CH];
        float m = -INFINITY;
#pragma unroll
        for (int d = 0; d < CH; d++) {
            float nk = fmaxf(sqrtf(nks[d]), EPSN);
            logit[d] = dot[d] / (nq * nk) * temp;
            m = fmaxf(m, logit[d]);
        }
        float sum = 0.f;
#pragma unroll
        for (int d = 0; d < CH; d++) { logit[d] = expf(logit[d] - m); sum += logit[d]; }
        const float inv = 1.f / sum;
#pragma unroll
        for (int d = 0; d < CH; d++) attn_sh[tid * 8 + d] = logit[d] * inv;
    }
    __syncthreads();

    // -- prologue 2: M[co][h2*8+d] = sum_c w_proj[co][h2*8+c]*attn[h2][c][d] --
    for (int idx = tid; idx < CC * CC; idx += 256) {
        int co = idx >> 6, j = idx & 63;
        int h2 = j >> 3, d = j & 7;
        float acc = 0.f;
#pragma unroll
        for (int cc = 0; cc < CH; cc++)
            acc += w_proj[co * CC + h2 * 8 + cc] * attn_sh[(h2 * 8 + cc) * 8 + d];
        M_sh[idx] = acc;
    }
    __syncthreads();

    // -- main: v GEMM --
    float vr[CC];
#pragma unroll
    for (int j = 0; j < CC; j++)
        vr[j] = __half2float(g_qkv[((size_t)(b * C3 + 2 * CC + j)) * SS + s]);

    float* op = out + ((size_t)b * CC) * SS + s;
    for (int co = 0; co < CC; co++) {
        const float4* m4 = (const float4*)(M_sh + co * CC);
        float acc = 0.f;
#pragma unroll
        for (int j = 0; j < CC / 4; j++) {
            float4 m = m4[j];
            acc += m.x * vr[4 * j + 0];
            acc += m.y * vr[4 * j + 1];
            acc += m.z * vr[4 * j + 2];
            acc += m.w * vr[4 * j + 3];
        }
        op[(size_t)co * SS] = acc;
    }
}

// ===========================================================================
extern "C" void kernel_launch(void* const* d_in, const int* in_sizes, int n_in,
                              void* d_out, int out_size)
{
    const float* x     = (const float*)d_in[0];
    const float* w_qkv = (const float*)d_in[1];
    const float* w_dw  = (const float*)d_in[2];
    const float* w_proj= (const float*)d_in[3];
    const float* temp  = (const float*)d_in[4];
    float* out = (float*)d_out;

    k1_pw  <<<dim3(SS / 256, BB), 256>>>(x, w_qkv);
    k2_dw  <<<dim3(ZZ / 8, C3, BB), 256>>>(w_dw);
    k3_red <<<dim3(NCHUNK, BB * HEADS), 256>>>();
    k5_out <<<dim3(SS / 256, BB), 256>>>(w_proj, temp, out);
}